// round 5
// baseline (speedup 1.0000x reference)
#include <cuda_runtime.h>
#include <math.h>

#define B_  32
#define NP_ 2048
#define NG_ 2048
#define L_  256
#define BIGF 1e18f
#define EPSF 1e-6f

#define LAMBDA_E_SUM       10.0f
#define LAMBDA_HIT         20.0f
#define LAMBDA_CHAMFER     0.001f
#define LAMBDA_HIT_ENTROPY 0.1f

typedef unsigned long long ull;

// ---------------- device scratch ----------------
__device__ float4 g_predPA[B_ * NP_ / 2];  // {-2x0,-2x1,-2y0,-2y1}
__device__ float4 g_predPB[B_ * NP_ / 2];  // {-2z0,-2z1, pn0, pn1}
__device__ float4 g_tgtPA [B_ * NG_ / 2];  // {x0,x1,y0,y1}
__device__ float4 g_tgtPB [B_ * NG_ / 2];  // {z0,z1, w0, w1} w=tn+BIG*!mask
__device__ float4 g_predS[B_ * NP_];       // {-2x,-2y,-2z, pn}
__device__ float4 g_tgtS [B_ * NG_];       // {  x,  y,  z, tn}
__device__ unsigned g_min1[B_ * NP_];      // encoded min, low 11 bits = idx
__device__ unsigned g_min2[B_ * NG_];
__device__ float g_acc[4];                 // 0 minD_pred 1 |dE| 2 minD_tgt*mask
__device__ float g_bat[128][8];            // [b*4+seg]: nhp,teh,nht,ent,kld
__device__ unsigned g_ticket;

// ---------------------------------------------------------------------------
__device__ __forceinline__ ull fma2(ull a, ull b, ull c) {
    ull d;
    asm("fma.rn.f32x2 %0, %1, %2, %3;" : "=l"(d) : "l"(a), "l"(b), "l"(c));
    return d;
}
__device__ __forceinline__ ull dup2(float x) {
    ull d;
    asm("mov.b64 %0, {%1, %1};" : "=l"(d) : "f"(x));
    return d;
}
__device__ __forceinline__ float2 unpack2(ull v) {
    float2 r;
    asm("mov.b64 {%0, %1}, %2;" : "=f"(r.x), "=f"(r.y) : "l"(v));
    return r;
}
__device__ __forceinline__ unsigned encodeF(float f) {
    unsigned u = __float_as_uint(f);
    return u ^ ((unsigned)((int)u >> 31) | 0x80000000u);
}
__device__ __forceinline__ float decodeF(unsigned key, unsigned& raw) {
    unsigned m = (key & 0x80000000u) ? 0x80000000u : 0xFFFFFFFFu;
    raw = key ^ m;
    return __uint_as_float(raw);
}

__device__ __forceinline__ float blockReduceSum(float v, float* sh) {
    const unsigned full = 0xffffffffu;
    #pragma unroll
    for (int o = 16; o > 0; o >>= 1) v += __shfl_down_sync(full, v, o);
    int w = threadIdx.x >> 5, l = threadIdx.x & 31;
    __syncthreads();
    if (l == 0) sh[w] = v;
    __syncthreads();
    if (threadIdx.x < 32) {
        v = (threadIdx.x < (blockDim.x >> 5)) ? sh[threadIdx.x] : 0.0f;
        #pragma unroll
        for (int o = 16; o > 0; o >>= 1) v += __shfl_down_sync(full, v, o);
    }
    return v;
}

// ---------------------------------------------------------------------------
// 256 blocks: [0,128) pred-side (+kld), [128,256) target-side. 1 pair/thread.
__global__ __launch_bounds__(256) void prep_kernel(
    const float* __restrict__ preds, const float* __restrict__ target,
    const float* __restrict__ mask,  const float* __restrict__ mu,
    const float* __restrict__ logvar) {
    __shared__ float shr[8];
    int blk = blockIdx.x, tid = threadIdx.x;

    // init: 65536 threads, one entry in each min array
    int gid = blk * 256 + tid;
    g_min1[gid] = 0xFFFFFFFFu;
    g_min2[gid] = 0xFFFFFFFFu;
    if (blk == 0 && tid < 4) g_acc[tid] = 0.0f;
    if (blk == 0 && tid == 4) g_ticket = 0u;

    if (blk < 128) {
        int b = blk >> 2, seg = blk & 3;
        int jp = seg * 256 + tid;
        int n = 2 * jp;
        const float* pb = preds + (size_t)b * 5 * NP_;

        float2 x = *(const float2*)(pb + n);
        float2 y = *(const float2*)(pb + NP_ + n);
        float2 z = *(const float2*)(pb + 2 * NP_ + n);
        float2 E = *(const float2*)(pb + 3 * NP_ + n);
        float2 h = *(const float2*)(pb + 4 * NP_ + n);
        float pn0 = x.x * x.x + y.x * y.x + z.x * z.x;
        float pn1 = x.y * x.y + y.y * y.y + z.y * z.y;
        g_predPA[b * 1024 + jp] = make_float4(-2.f * x.x, -2.f * x.y, -2.f * y.x, -2.f * y.y);
        g_predPB[b * 1024 + jp] = make_float4(-2.f * z.x, -2.f * z.y, pn0, pn1);
        g_predS[b * NP_ + n]     = make_float4(-2.f * x.x, -2.f * y.x, -2.f * z.x, pn0);
        g_predS[b * NP_ + n + 1] = make_float4(-2.f * x.y, -2.f * y.y, -2.f * z.y, pn1);
        float nhp = h.x + h.y;
        float teh = E.x * h.x + E.y * h.y;
        float ent = -(h.x * __logf(h.x + EPSF) + (1.f - h.x) * __logf(1.f - h.x + EPSF))
                    -(h.y * __logf(h.y + EPSF) + (1.f - h.y) * __logf(1.f - h.y + EPSF));
        float kld = 0.f;
        if (seg == 0) {
            float m_ = mu[b * L_ + tid], lv = logvar[b * L_ + tid];
            kld = 1.f + lv - m_ * m_ - __expf(lv);
        }
        nhp = blockReduceSum(nhp, shr);
        teh = blockReduceSum(teh, shr);
        ent = blockReduceSum(ent, shr);
        kld = blockReduceSum(kld, shr);
        if (tid == 0) {
            float* s = g_bat[b * 4 + seg];
            s[0] = nhp; s[1] = teh; s[3] = ent; s[4] = kld;
        }
    } else {
        int w = blk - 128;
        int b = w >> 2, seg = w & 3;
        int jp = seg * 256 + tid;
        int n = 2 * jp;
        const float* tb = target + (size_t)b * 4 * NG_;
        const float* mb = mask   + (size_t)b * NG_;

        float2 tx = *(const float2*)(tb + n);
        float2 ty = *(const float2*)(tb + NG_ + n);
        float2 tz = *(const float2*)(tb + 2 * NG_ + n);
        float2 mk = *(const float2*)(mb + n);
        float tn0 = tx.x * tx.x + ty.x * ty.x + tz.x * tz.x;
        float tn1 = tx.y * tx.y + ty.y * ty.y + tz.y * tz.y;
        g_tgtPA[b * 1024 + jp] = make_float4(tx.x, tx.y, ty.x, ty.y);
        g_tgtPB[b * 1024 + jp] = make_float4(tz.x, tz.y,
                                             tn0 + (mk.x == 0.f ? BIGF : 0.f),
                                             tn1 + (mk.y == 0.f ? BIGF : 0.f));
        g_tgtS[b * NG_ + n]     = make_float4(tx.x, ty.x, tz.x, tn0);
        g_tgtS[b * NG_ + n + 1] = make_float4(tx.y, ty.y, tz.y, tn1);
        float nht = blockReduceSum(mk.x + mk.y, shr);
        if (tid == 0) g_bat[b * 4 + seg][2] = nht;
    }
}

// ---------------------------------------------------------------------------
// Fused chamfer. 2048 blocks (fine-grained to kill wave quantization):
//   [0,1024)    pass1: pred->tgt, argmin in low 11 mantissa bits
//   [1024,2048) pass2: tgt->pred, plain min
// Each block: 2048 register points (8/thread) x one 64-point smem chunk.
__global__ __launch_bounds__(256, 2) void chamfer_kernel() {
    __shared__ ulonglong2 shA[32], shB[32];
    int blk = blockIdx.x, tid = threadIdx.x;
    bool isP1 = blk < 1024;
    int w = isP1 ? blk : blk - 1024;
    int b = w >> 5, chunk = w & 31;

    if (tid < 32) {
        const float4* PA = isP1 ? g_tgtPA : g_predPA;
        const float4* PB = isP1 ? g_tgtPB : g_predPB;
        float4 a = PA[b * 1024 + chunk * 32 + tid];
        float4 v = PB[b * 1024 + chunk * 32 + tid];
        shA[tid] = *(ulonglong2*)&a;
        shB[tid] = *(ulonglong2*)&v;
    }
    __syncthreads();

    if (isP1) {
        int pbase = b * NP_ + tid;
        ull ax2[8], ay2[8], az2[8];
        #pragma unroll
        for (int i = 0; i < 8; i++) {
            float4 p = g_predS[pbase + i * 256];
            ax2[i] = dup2(p.x); ay2[i] = dup2(p.y); az2[i] = dup2(p.z);
        }
        float bl[8], bh[8];
        #pragma unroll
        for (int i = 0; i < 8; i++) { bl[i] = 3.4e38f; bh[i] = 3.4e38f; }

        unsigned jlo = (unsigned)(chunk * 64);
        #pragma unroll 4
        for (int j = 0; j < 32; j++) {
            ulonglong2 A = shA[j], Bv = shB[j];
            unsigned jhi = jlo | 1u;
            #pragma unroll
            for (int i = 0; i < 8; i++) {
                ull t = fma2(az2[i], Bv.x, Bv.y);
                t = fma2(ay2[i], A.y, t);
                t = fma2(ax2[i], A.x, t);
                float2 v = unpack2(t);
                unsigned elo = (__float_as_uint(v.x) & 0xFFFFF800u) | jlo;
                unsigned ehi = (__float_as_uint(v.y) & 0xFFFFF800u) | jhi;
                bl[i] = fminf(bl[i], __uint_as_float(elo));
                bh[i] = fminf(bh[i], __uint_as_float(ehi));
            }
            jlo += 2;
        }
        #pragma unroll
        for (int i = 0; i < 8; i++)
            atomicMin(&g_min1[pbase + i * 256], encodeF(fminf(bl[i], bh[i])));
    } else {
        int tbase = b * NG_ + tid;
        ull tx2[8], ty2[8], tz2[8];
        #pragma unroll
        for (int i = 0; i < 8; i++) {
            float4 t = g_tgtS[tbase + i * 256];
            tx2[i] = dup2(t.x); ty2[i] = dup2(t.y); tz2[i] = dup2(t.z);
        }
        float bl[8], bh[8];
        #pragma unroll
        for (int i = 0; i < 8; i++) { bl[i] = 3.4e38f; bh[i] = 3.4e38f; }

        #pragma unroll 4
        for (int j = 0; j < 32; j++) {
            ulonglong2 A = shA[j], Bv = shB[j];
            #pragma unroll
            for (int i = 0; i < 8; i++) {
                ull t = fma2(tz2[i], Bv.x, Bv.y);
                t = fma2(ty2[i], A.y, t);
                t = fma2(tx2[i], A.x, t);
                float2 v = unpack2(t);
                bl[i] = fminf(bl[i], v.x);
                bh[i] = fminf(bh[i], v.y);
            }
        }
        #pragma unroll
        for (int i = 0; i < 8; i++)
            atomicMin(&g_min2[tbase + i * 256], encodeF(fminf(bl[i], bh[i])));
    }
}

// ---------------------------------------------------------------------------
// Combine + final (last block via ticket computes the scalar losses).
__global__ __launch_bounds__(256) void combine_kernel(
    const float* __restrict__ preds, const float* __restrict__ target,
    const float* __restrict__ mask,  const float* __restrict__ e_init,
    const float* __restrict__ kl_weight, float* __restrict__ out, int out_size) {
    __shared__ float shr[8];
    __shared__ int s_last;
    int blk = blockIdx.x, tid = threadIdx.x;

    if (blk < 128) {
        float md = 0.f, le = 0.f;
        #pragma unroll
        for (int r = 0; r < 2; r++) {
            int n = blk * 512 + r * 256 + tid;
            unsigned raw;
            float best = decodeF(g_min1[n], raw);
            int idx = (int)(raw & 0x7FFu);
            int b = n >> 11, nn = n & (NP_ - 1);
            md += fmaxf(g_predS[n].w + best, 0.f);
            float tE = target[(size_t)b * 4 * NG_ + 3 * NG_ + idx];
            float pE = preds[(size_t)b * 5 * NP_ + 3 * NP_ + nn];
            le += fabsf(pE - tE);
        }
        md = blockReduceSum(md, shr);
        le = blockReduceSum(le, shr);
        if (tid == 0) { atomicAdd(&g_acc[0], md); atomicAdd(&g_acc[1], le); }
    } else {
        float s = 0.f;
        #pragma unroll
        for (int r = 0; r < 2; r++) {
            int m = (blk - 128) * 512 + r * 256 + tid;
            unsigned raw;
            float best = decodeF(g_min2[m], raw);
            s += fmaxf(g_tgtS[m].w + best, 0.f) * mask[m];
        }
        s = blockReduceSum(s, shr);
        if (tid == 0) atomicAdd(&g_acc[2], s);
    }

    if (tid == 0) {
        __threadfence();
        unsigned t = atomicAdd(&g_ticket, 1u);
        s_last = (t == 255u);
    }
    __syncthreads();
    if (!s_last) return;

    int t = tid;
    float dh2 = 0.f, de2 = 0.f, ent = 0.f, kld = 0.f, nhtTot = 0.f;
    if (t < B_) {
        float nhp = 0.f, teh = 0.f, nht = 0.f;
        #pragma unroll
        for (int s2 = 0; s2 < 4; s2++) {
            const float* sb = g_bat[t * 4 + s2];
            nhp += sb[0]; teh += sb[1]; nht += sb[2];
            ent += sb[3]; kld += sb[4];
        }
        float dh = nhp - nht;
        float de = teh - e_init[t];
        dh2 = dh * dh; de2 = de * de; nhtTot = nht;
    }
    if (t < 32) {
        const unsigned full = 0xffffffffu;
        #pragma unroll
        for (int o = 16; o > 0; o >>= 1) {
            dh2 += __shfl_down_sync(full, dh2, o);
            de2 += __shfl_down_sync(full, de2, o);
            ent += __shfl_down_sync(full, ent, o);
            kld += __shfl_down_sync(full, kld, o);
            nhtTot += __shfl_down_sync(full, nhtTot, o);
        }
        if (t == 0) {
            float a0 = atomicAdd(&g_acc[0], 0.f);
            float a1 = atomicAdd(&g_acc[1], 0.f);
            float a2 = atomicAdd(&g_acc[2], 0.f);
            float chamP = a0 / (float)(B_ * NP_);
            float chamT = a2 / nhtTot;
            float loss_chamf = (chamT + chamP) * LAMBDA_CHAMFER;
            float localE = a1 / (float)(B_ * NP_);
            float ge   = LAMBDA_E_SUM * de2 / (float)B_;
            float hit  = LAMBDA_HIT   * dh2 / (float)B_;
            float entr = LAMBDA_HIT_ENTROPY * ent / (float)(B_ * NP_);
            float kl   = kl_weight[0] * (-0.5f * kld / (float)B_);
            float total = loss_chamf + localE + kl + ge + hit + entr;

            if (out_size >= 6) {
                out[0] = total;
                out[1] = loss_chamf;
                out[2] = localE;
                out[3] = ge;
                out[4] = hit;
                out[5] = kl;
            } else if (out_size == 5) {
                out[0] = loss_chamf; out[1] = localE; out[2] = ge;
                out[3] = hit;        out[4] = kl;
            } else {
                out[0] = total;
            }
        }
    }
}

// ---------------------------------------------------------------------------
extern "C" void kernel_launch(void* const* d_in, const int* in_sizes, int n_in,
                              void* d_out, int out_size) {
    const float* preds  = (const float*)d_in[0];
    const float* target = (const float*)d_in[1];
    const float* tmask  = (const float*)d_in[2];
    const float* mu     = (const float*)d_in[3];
    const float* logvar = (const float*)d_in[4];
    const float* e_init = (const float*)d_in[5];
    const float* klw    = (const float*)d_in[6];
    float* out = (float*)d_out;

    prep_kernel<<<256, 256>>>(preds, target, tmask, mu, logvar);
    chamfer_kernel<<<2048, 256>>>();
    combine_kernel<<<256, 256>>>(preds, target, tmask, e_init, klw, out, out_size);
}